// round 2
// baseline (speedup 1.0000x reference)
#include <cuda_runtime.h>

// NonParaGCNConv: h = scatter_add_dst( x[src] * norm[src]*norm[dst] ) + 0.5*x
// norm = rsqrt(max(out_degree, 1))
//
// Inputs (metadata order): x [N*64] f32, src [E] i32, dst [E] i32
// Output: [N*64] f32

#define FDIM 64
#define FDIM4 16          // float4 chunks per node row
#define MAXN 100352       // >= N (100000), scratch bound

__device__ int   g_deg[MAXN];
__device__ float g_norm[MAXN];

// ---------------------------------------------------------------------------
__global__ void k_zero_deg(int n) {
    int i = blockIdx.x * blockDim.x + threadIdx.x;
    if (i < n) g_deg[i] = 0;
}

__global__ void k_degree(const int* __restrict__ src, int e) {
    int i = blockIdx.x * blockDim.x + threadIdx.x;
    if (i < e) atomicAdd(&g_deg[src[i]], 1);
}

// norm[i] = rsqrt(max(deg,1)); out = 0.5 * x  (also un-poisons d_out)
__global__ void k_norm_init(const float4* __restrict__ x4,
                            float4* __restrict__ out4, int n) {
    int gid  = blockIdx.x * blockDim.x + threadIdx.x;
    int node = gid >> 4;
    int c    = gid & 15;
    if (node >= n) return;
    if (c == 0) {
        float dg = (float)g_deg[node];
        g_norm[node] = rsqrtf(fmaxf(dg, 1.0f));
    }
    float4 v = x4[(size_t)node * FDIM4 + c];
    v.x *= 0.5f; v.y *= 0.5f; v.z *= 0.5f; v.w *= 0.5f;
    out4[(size_t)node * FDIM4 + c] = v;
}

// 16 threads per edge; each thread handles one float4 (4 feature dims).
// Gather x[src] from L2 (x fits in L2), scatter-add into out[dst] via REDG.
__global__ void k_edge(const float4* __restrict__ x4,
                       const int* __restrict__ src,
                       const int* __restrict__ dst,
                       float* __restrict__ out, int e) {
    long long gid = (long long)blockIdx.x * blockDim.x + threadIdx.x;
    int eid = (int)(gid >> 4);
    int c   = (int)(gid & 15);
    if (eid >= e) return;

    int s = __ldg(src + eid);
    int d = __ldg(dst + eid);
    float w = __ldg(&g_norm[s]) * __ldg(&g_norm[d]);

    float4 v = x4[(size_t)s * FDIM4 + c];
    float* o = out + (size_t)d * FDIM + c * 4;
    atomicAdd(o + 0, v.x * w);
    atomicAdd(o + 1, v.y * w);
    atomicAdd(o + 2, v.z * w);
    atomicAdd(o + 3, v.w * w);
}

// ---------------------------------------------------------------------------
extern "C" void kernel_launch(void* const* d_in, const int* in_sizes, int n_in,
                              void* d_out, int out_size) {
    const float* x   = (const float*)d_in[0];
    const int*   src = (const int*)d_in[1];
    const int*   dst = (const int*)d_in[2];
    float*       out = (float*)d_out;

    int n = in_sizes[0] / FDIM;   // 100000
    int e = in_sizes[1];          // 1250000

    const int TB = 256;

    // 1) zero degree counters (scratch must be re-zeroed every launch)
    k_zero_deg<<<(n + TB - 1) / TB, TB>>>(n);

    // 2) out-degree via int atomics
    k_degree<<<(e + TB - 1) / TB, TB>>>(src, e);

    // 3) norm + residual init (out = 0.5*x)
    {
        long long t = (long long)n * FDIM4;
        k_norm_init<<<(unsigned)((t + TB - 1) / TB), TB>>>(
            (const float4*)x, (float4*)out, n);
    }

    // 4) edge scatter-add
    {
        long long t = (long long)e * FDIM4;
        k_edge<<<(unsigned)((t + TB - 1) / TB), TB>>>(
            (const float4*)x, src, dst, out, e);
    }
}

// round 3
// speedup vs baseline: 2.1567x; 2.1567x over previous
#include <cuda_runtime.h>

// NonParaGCNConv: h = scatter_add_dst( x[src] * norm[src]*norm[dst] ) + 0.5*x
// norm = rsqrt(max(out_degree, 1))
//
// Inputs (metadata order): x [N*64] f32, src [E] i32, dst [E] i32
// Output: [N*64] f32

#define FDIM 64
#define FDIM4 16          // float4 chunks per node row
#define MAXN 100352       // >= N (100000), scratch bound

__device__ int   g_deg[MAXN];
__device__ float g_norm[MAXN];

// ---------------------------------------------------------------------------
__global__ void k_zero_deg(int n) {
    int i = blockIdx.x * blockDim.x + threadIdx.x;
    if (i < n) g_deg[i] = 0;
}

__global__ void k_degree(const int* __restrict__ src, int e) {
    int i = blockIdx.x * blockDim.x + threadIdx.x;
    if (i < e) atomicAdd(&g_deg[src[i]], 1);
}

// norm[i] = rsqrt(max(deg,1)); out = 0.5 * x  (also un-poisons d_out)
__global__ void k_norm_init(const float4* __restrict__ x4,
                            float4* __restrict__ out4, int n) {
    int gid  = blockIdx.x * blockDim.x + threadIdx.x;
    int node = gid >> 4;
    int c    = gid & 15;
    if (node >= n) return;
    if (c == 0) {
        float dg = (float)g_deg[node];
        g_norm[node] = rsqrtf(fmaxf(dg, 1.0f));
    }
    float4 v = x4[(size_t)node * FDIM4 + c];
    v.x *= 0.5f; v.y *= 0.5f; v.z *= 0.5f; v.w *= 0.5f;
    out4[(size_t)node * FDIM4 + c] = v;
}

// 16 threads (one half-warp) per edge; each thread owns one float4 chunk.
// Leader lane of each half-warp loads src/dst + norms, computes the edge
// weight, and broadcasts via SHFL. Accumulation uses a single vector
// reduction (red.global.add.v4.f32) instead of 4 scalar atomics.
__global__ void k_edge(const float4* __restrict__ x4,
                       const int* __restrict__ src,
                       const int* __restrict__ dst,
                       float* __restrict__ out, int e) {
    long long gid = (long long)blockIdx.x * blockDim.x + threadIdx.x;
    int eid  = (int)(gid >> 4);
    int lane = threadIdx.x & 31;
    int c    = lane & 15;
    int lead = lane & 16;          // leader lane of this half-warp (0 or 16)
    if (eid >= e) return;

    int s = 0, d = 0;
    float w = 0.0f;
    if (c == 0) {
        s = __ldg(src + eid);
        d = __ldg(dst + eid);
        w = __ldg(&g_norm[s]) * __ldg(&g_norm[d]);
    }
    s = __shfl_sync(0xffffffffu, s, lead);
    d = __shfl_sync(0xffffffffu, d, lead);
    w = __shfl_sync(0xffffffffu, w, lead);

    float4 v = x4[(size_t)s * FDIM4 + c];
    float* o = out + (size_t)d * FDIM + c * 4;   // 16B-aligned
    asm volatile("red.global.add.v4.f32 [%0], {%1, %2, %3, %4};"
                 :: "l"(o), "f"(v.x * w), "f"(v.y * w),
                    "f"(v.z * w), "f"(v.w * w)
                 : "memory");
}

// ---------------------------------------------------------------------------
extern "C" void kernel_launch(void* const* d_in, const int* in_sizes, int n_in,
                              void* d_out, int out_size) {
    const float* x   = (const float*)d_in[0];
    const int*   src = (const int*)d_in[1];
    const int*   dst = (const int*)d_in[2];
    float*       out = (float*)d_out;

    int n = in_sizes[0] / FDIM;   // 100000
    int e = in_sizes[1];          // 1250000

    const int TB = 256;

    // 1) zero degree counters (scratch must be re-zeroed every launch)
    k_zero_deg<<<(n + TB - 1) / TB, TB>>>(n);

    // 2) out-degree via int atomics
    k_degree<<<(e + TB - 1) / TB, TB>>>(src, e);

    // 3) norm + residual init (out = 0.5*x)
    {
        long long t = (long long)n * FDIM4;
        k_norm_init<<<(unsigned)((t + TB - 1) / TB), TB>>>(
            (const float4*)x, (float4*)out, n);
    }

    // 4) edge scatter-add (vector reductions)
    {
        long long t = (long long)e * FDIM4;
        k_edge<<<(unsigned)((t + TB - 1) / TB), TB>>>(
            (const float4*)x, src, dst, out, e);
    }
}

// round 4
// speedup vs baseline: 2.2517x; 1.0441x over previous
#include <cuda_runtime.h>

// NonParaGCNConv: h = scatter_add_dst( x[src] * norm[src]*norm[dst] ) + 0.5*x
// norm = rsqrt(max(out_degree, 1))
//
// Inputs (metadata order): x [N*64] f32, src [E] i32, dst [E] i32
// Output: [N*64] f32

#define FDIM 64
#define FDIM4 16          // float4 chunks per node row
#define MAXN 100352       // >= N (100000), scratch bound

__device__ int   g_deg[MAXN];
__device__ float g_norm[MAXN];

// ---------------------------------------------------------------------------
__global__ void k_zero_deg(int n) {
    int i = blockIdx.x * blockDim.x + threadIdx.x;
    if (i < n) g_deg[i] = 0;
}

__global__ void k_degree(const int* __restrict__ src, int e) {
    int i = blockIdx.x * blockDim.x + threadIdx.x;
    if (i < e) atomicAdd(&g_deg[src[i]], 1);
}

// norm[i] = rsqrt(max(deg,1)); out = 0.5 * x  (also un-poisons d_out)
__global__ void k_norm_init(const float4* __restrict__ x4,
                            float4* __restrict__ out4, int n) {
    int gid  = blockIdx.x * blockDim.x + threadIdx.x;
    int node = gid >> 4;
    int c    = gid & 15;
    if (node >= n) return;
    if (c == 0) {
        float dg = (float)g_deg[node];
        g_norm[node] = rsqrtf(fmaxf(dg, 1.0f));
    }
    float4 v = x4[(size_t)node * FDIM4 + c];
    v.x *= 0.5f; v.y *= 0.5f; v.z *= 0.5f; v.w *= 0.5f;
    out4[(size_t)node * FDIM4 + c] = v;
}

__device__ __forceinline__ void red_v4(float* o, float4 v, float w) {
    asm volatile("red.global.add.v4.f32 [%0], {%1, %2, %3, %4};"
                 :: "l"(o), "f"(v.x * w), "f"(v.y * w),
                    "f"(v.z * w), "f"(v.w * w)
                 : "memory");
}

// 16 threads (one half-warp) per GROUP of 4 edges; each thread owns one
// float4 chunk of all 4 edges. Leader lane loads int4 src/dst + norms,
// computes 4 edge weights, broadcasts via SHFL. Each thread then issues
// 4 independent LDG.128 gathers (MLP=4) and 4 RED.128 reductions.
__global__ void k_edge(const float4* __restrict__ x4,
                       const int* __restrict__ src,
                       const int* __restrict__ dst,
                       float* __restrict__ out, int e) {
    long long gid = (long long)blockIdx.x * blockDim.x + threadIdx.x;
    int grp  = (int)(gid >> 4);        // group of 4 edges
    int base = grp * 4;
    if (base >= e) return;

    int lane = threadIdx.x & 31;
    int c    = lane & 15;
    int lead = lane & 16;              // leader lane of this half-warp

    int4  ss = make_int4(0, 0, 0, 0);
    int4  dd = make_int4(0, 0, 0, 0);
    float w0 = 0.f, w1 = 0.f, w2 = 0.f, w3 = 0.f;

    if (c == 0) {
        if (base + 3 < e) {            // fast path: vector index loads
            ss = __ldg((const int4*)(src + base));
            dd = __ldg((const int4*)(dst + base));
        } else {                        // tail: guarded scalar loads
            ss.x = __ldg(src + base);            dd.x = __ldg(dst + base);
            ss.y = (base + 1 < e) ? __ldg(src + base + 1) : ss.x;
            dd.y = (base + 1 < e) ? __ldg(dst + base + 1) : dd.x;
            ss.z = (base + 2 < e) ? __ldg(src + base + 2) : ss.x;
            dd.z = (base + 2 < e) ? __ldg(dst + base + 2) : dd.x;
            ss.w = ss.x; dd.w = dd.x;
        }
        w0 = __ldg(&g_norm[ss.x]) * __ldg(&g_norm[dd.x]);
        w1 = __ldg(&g_norm[ss.y]) * __ldg(&g_norm[dd.y]);
        w2 = __ldg(&g_norm[ss.z]) * __ldg(&g_norm[dd.z]);
        w3 = __ldg(&g_norm[ss.w]) * __ldg(&g_norm[dd.w]);
        if (base + 1 >= e) w1 = 0.f;
        if (base + 2 >= e) w2 = 0.f;
        if (base + 3 >= e) w3 = 0.f;
    }
    ss.x = __shfl_sync(0xffffffffu, ss.x, lead);
    ss.y = __shfl_sync(0xffffffffu, ss.y, lead);
    ss.z = __shfl_sync(0xffffffffu, ss.z, lead);
    ss.w = __shfl_sync(0xffffffffu, ss.w, lead);
    dd.x = __shfl_sync(0xffffffffu, dd.x, lead);
    dd.y = __shfl_sync(0xffffffffu, dd.y, lead);
    dd.z = __shfl_sync(0xffffffffu, dd.z, lead);
    dd.w = __shfl_sync(0xffffffffu, dd.w, lead);
    w0   = __shfl_sync(0xffffffffu, w0, lead);
    w1   = __shfl_sync(0xffffffffu, w1, lead);
    w2   = __shfl_sync(0xffffffffu, w2, lead);
    w3   = __shfl_sync(0xffffffffu, w3, lead);

    // 4 independent gathers (MLP=4)
    float4 v0 = x4[(size_t)ss.x * FDIM4 + c];
    float4 v1 = x4[(size_t)ss.y * FDIM4 + c];
    float4 v2 = x4[(size_t)ss.z * FDIM4 + c];
    float4 v3 = x4[(size_t)ss.w * FDIM4 + c];

    int co = c * 4;
    red_v4(out + (size_t)dd.x * FDIM + co, v0, w0);
    if (w1 != 0.f || base + 1 < e) red_v4(out + (size_t)dd.y * FDIM + co, v1, w1);
    if (w2 != 0.f || base + 2 < e) red_v4(out + (size_t)dd.z * FDIM + co, v2, w2);
    if (w3 != 0.f || base + 3 < e) red_v4(out + (size_t)dd.w * FDIM + co, v3, w3);
}

// ---------------------------------------------------------------------------
extern "C" void kernel_launch(void* const* d_in, const int* in_sizes, int n_in,
                              void* d_out, int out_size) {
    const float* x   = (const float*)d_in[0];
    const int*   src = (const int*)d_in[1];
    const int*   dst = (const int*)d_in[2];
    float*       out = (float*)d_out;

    int n = in_sizes[0] / FDIM;   // 100000
    int e = in_sizes[1];          // 1250000

    const int TB = 256;

    // 1) zero degree counters (scratch must be re-zeroed every launch)
    k_zero_deg<<<(n + TB - 1) / TB, TB>>>(n);

    // 2) out-degree via int atomics
    k_degree<<<(e + TB - 1) / TB, TB>>>(src, e);

    // 3) norm + residual init (out = 0.5*x)
    {
        long long t = (long long)n * FDIM4;
        k_norm_init<<<(unsigned)((t + TB - 1) / TB), TB>>>(
            (const float4*)x, (float4*)out, n);
    }

    // 4) edge scatter-add, 4 edges per 16-lane group (MLP=4)
    {
        int groups = (e + 3) / 4;
        long long t = (long long)groups * 16;
        k_edge<<<(unsigned)((t + TB - 1) / TB), TB>>>(
            (const float4*)x, src, dst, out, e);
    }
}

// round 5
// speedup vs baseline: 2.2589x; 1.0032x over previous
#include <cuda_runtime.h>

// NonParaGCNConv: h = scatter_add_dst( x[src] * norm[src]*norm[dst] ) + 0.5*x
// norm = rsqrt(max(out_degree, 1))
//
// Inputs (metadata order): x [N*64] f32, src [E] i32, dst [E] i32
// Output: [N*64] f32

#define FDIM 64
#define FDIM4 16          // float4 chunks per node row
#define MAXN 100352       // >= N (100000), scratch bound
#define UNROLL 8

__device__ int   g_deg[MAXN];
__device__ float g_norm[MAXN];

// ---------------------------------------------------------------------------
__global__ void k_degree(const int* __restrict__ src, int e) {
    int i4 = blockIdx.x * blockDim.x + threadIdx.x;
    int base = i4 * 4;
    if (base + 3 < e) {
        int4 s = __ldg((const int4*)(src + base));
        atomicAdd(&g_deg[s.x], 1);
        atomicAdd(&g_deg[s.y], 1);
        atomicAdd(&g_deg[s.z], 1);
        atomicAdd(&g_deg[s.w], 1);
    } else {
        for (int i = base; i < e; i++) atomicAdd(&g_deg[__ldg(src + i)], 1);
    }
}

// norm[i] = rsqrt(max(deg,1)); out = 0.5 * x  (also un-poisons d_out)
__global__ void k_norm_init(const float4* __restrict__ x4,
                            float4* __restrict__ out4, int n) {
    int gid  = blockIdx.x * blockDim.x + threadIdx.x;
    int node = gid >> 4;
    int c    = gid & 15;
    if (node >= n) return;
    if (c == 0) {
        float dg = (float)g_deg[node];
        g_norm[node] = rsqrtf(fmaxf(dg, 1.0f));
    }
    float4 v = x4[(size_t)node * FDIM4 + c];
    v.x *= 0.5f; v.y *= 0.5f; v.z *= 0.5f; v.w *= 0.5f;
    out4[(size_t)node * FDIM4 + c] = v;
}

__device__ __forceinline__ void red_v4(float* o, float4 v, float w) {
    asm volatile("red.global.add.v4.f32 [%0], {%1, %2, %3, %4};"
                 :: "l"(o), "f"(v.x * w), "f"(v.y * w),
                    "f"(v.z * w), "f"(v.w * w)
                 : "memory");
}

// 16 threads (one half-warp) per GROUP of 8 edges; each thread owns one
// float4 chunk of all 8 edges. Leader lane loads 2x int4 src/dst + norms,
// computes 8 edge weights, broadcasts via SHFL. Each thread then issues
// 8 independent LDG.128 gathers (MLP=8), then 8 RED.128 reductions.
__global__ void k_edge(const float4* __restrict__ x4,
                       const int* __restrict__ src,
                       const int* __restrict__ dst,
                       float* __restrict__ out, int e) {
    long long gid = (long long)blockIdx.x * blockDim.x + threadIdx.x;
    int grp  = (int)(gid >> 4);
    int base = grp * UNROLL;
    if (base >= e) return;

    int lane = threadIdx.x & 31;
    int c    = lane & 15;
    int lead = lane & 16;              // leader lane of this half-warp

    int   s[UNROLL], d[UNROLL];
    float w[UNROLL];

    if (c == 0) {
        if (base + UNROLL - 1 < e) {   // fast path: vector index loads
            int4 sa = __ldg((const int4*)(src + base));
            int4 sb = __ldg((const int4*)(src + base + 4));
            int4 da = __ldg((const int4*)(dst + base));
            int4 db = __ldg((const int4*)(dst + base + 4));
            s[0]=sa.x; s[1]=sa.y; s[2]=sa.z; s[3]=sa.w;
            s[4]=sb.x; s[5]=sb.y; s[6]=sb.z; s[7]=sb.w;
            d[0]=da.x; d[1]=da.y; d[2]=da.z; d[3]=da.w;
            d[4]=db.x; d[5]=db.y; d[6]=db.z; d[7]=db.w;
            #pragma unroll
            for (int i = 0; i < UNROLL; i++)
                w[i] = __ldg(&g_norm[s[i]]) * __ldg(&g_norm[d[i]]);
        } else {                        // tail: guarded scalar loads
            #pragma unroll
            for (int i = 0; i < UNROLL; i++) {
                if (base + i < e) {
                    s[i] = __ldg(src + base + i);
                    d[i] = __ldg(dst + base + i);
                    w[i] = __ldg(&g_norm[s[i]]) * __ldg(&g_norm[d[i]]);
                } else {
                    s[i] = s[0]; d[i] = d[0]; w[i] = 0.f;
                }
            }
        }
    }
    #pragma unroll
    for (int i = 0; i < UNROLL; i++) {
        s[i] = __shfl_sync(0xffffffffu, s[i], lead);
        d[i] = __shfl_sync(0xffffffffu, d[i], lead);
        w[i] = __shfl_sync(0xffffffffu, w[i], lead);
    }

    // 8 independent gathers (MLP=8)
    float4 v[UNROLL];
    #pragma unroll
    for (int i = 0; i < UNROLL; i++)
        v[i] = x4[(size_t)s[i] * FDIM4 + c];

    int co = c * 4;
    #pragma unroll
    for (int i = 0; i < UNROLL; i++)
        if (base + i < e)
            red_v4(out + (size_t)d[i] * FDIM + co, v[i], w[i]);
}

// ---------------------------------------------------------------------------
extern "C" void kernel_launch(void* const* d_in, const int* in_sizes, int n_in,
                              void* d_out, int out_size) {
    const float* x   = (const float*)d_in[0];
    const int*   src = (const int*)d_in[1];
    const int*   dst = (const int*)d_in[2];
    float*       out = (float*)d_out;

    int n = in_sizes[0] / FDIM;   // 100000
    int e = in_sizes[1];          // 1250000

    const int TB = 256;

    // 1) zero degree counters via async memset (graph-capturable, no launch)
    void* deg_ptr = nullptr;
    cudaGetSymbolAddress(&deg_ptr, g_deg);
    cudaMemsetAsync(deg_ptr, 0, (size_t)n * sizeof(int), 0);

    // 2) out-degree via int atomics (int4 index loads)
    {
        int t = (e + 3) / 4;
        k_degree<<<(t + TB - 1) / TB, TB>>>(src, e);
    }

    // 3) norm + residual init (out = 0.5*x)
    {
        long long t = (long long)n * FDIM4;
        k_norm_init<<<(unsigned)((t + TB - 1) / TB), TB>>>(
            (const float4*)x, (float4*)out, n);
    }

    // 4) edge scatter-add, 8 edges per 16-lane group (MLP=8)
    {
        int groups = (e + UNROLL - 1) / UNROLL;
        long long t = (long long)groups * 16;
        k_edge<<<(unsigned)((t + TB - 1) / TB), TB>>>(
            (const float4*)x, src, dst, out, e);
    }
}